// round 2
// baseline (speedup 1.0000x reference)
#include <cuda_runtime.h>
#include <math.h>

// Problem constants
#define Bsz  2
#define Ssz  2048
#define Dsz  1024
#define Hsz  16
#define DHsz 64
#define Msz  (Bsz * Ssz)   // 4096 rows

// Scratch: q/k/v/ctx all stored as [B*S, H*DH] row-major (head-blocked columns).
__device__ float g_q[Msz * Dsz];
__device__ float g_k[Msz * Dsz];
__device__ float g_v[Msz * Dsz];
__device__ float g_ctx[Msz * Dsz];

// ---------------------------------------------------------------------------
// GEMM + bias: C[M,N] = A[M,K] @ W + bias
//   HB=1: W is head-blocked [H, K, DH]  (element (k,n) at ((n>>6)*K + k)*64 + (n&63))
//   HB=0: W is plain row-major [K, N]
// 128x128 tile, BK=8, 256 threads, 8x8 per thread.
// ---------------------------------------------------------------------------
template <int HB>
__global__ __launch_bounds__(256)
void gemm_bias(const float* __restrict__ A, const float* __restrict__ W,
               const float* __restrict__ bias, float* __restrict__ C,
               int M, int N, int K)
{
    const int BM = 128, BN = 128, BK = 8;
    __shared__ float As[BK][BM];   // stored transposed
    __shared__ float Bs[BK][BN];

    int tid  = threadIdx.x;
    int cRow = blockIdx.y * BM;
    int cCol = blockIdx.x * BN;

    int aRow = tid >> 1;            // 0..127
    int aCol = (tid & 1) * 4;       // 0 or 4
    int bRow = tid >> 5;            // 0..7
    int bCol = (tid & 31) * 4;      // 0..124

    int tr = (tid >> 4) * 8;        // 0..120
    int tc = (tid & 15) * 8;        // 0..120

    float acc[8][8];
#pragma unroll
    for (int i = 0; i < 8; i++)
#pragma unroll
        for (int j = 0; j < 8; j++) acc[i][j] = 0.f;

    const float* Arow = A + (size_t)(cRow + aRow) * K;

    for (int k0 = 0; k0 < K; k0 += BK) {
        // load A tile (transposed into SMEM)
        float4 a4 = *(const float4*)(Arow + k0 + aCol);
        As[aCol + 0][aRow] = a4.x;
        As[aCol + 1][aRow] = a4.y;
        As[aCol + 2][aRow] = a4.z;
        As[aCol + 3][aRow] = a4.w;

        // load W tile
        int n  = cCol + bCol;
        int kk = k0 + bRow;
        const float* wp;
        if (HB) wp = W + ((size_t)(n >> 6) * K + kk) * DHsz + (n & 63);
        else    wp = W + (size_t)kk * N + n;
        *(float4*)&Bs[bRow][bCol] = *(const float4*)wp;

        __syncthreads();

#pragma unroll
        for (int kq = 0; kq < BK; kq++) {
            float4 m0 = *(float4*)&As[kq][tr];
            float4 m1 = *(float4*)&As[kq][tr + 4];
            float4 n0 = *(float4*)&Bs[kq][tc];
            float4 n1 = *(float4*)&Bs[kq][tc + 4];
            float rm[8] = {m0.x, m0.y, m0.z, m0.w, m1.x, m1.y, m1.z, m1.w};
            float rn[8] = {n0.x, n0.y, n0.z, n0.w, n1.x, n1.y, n1.z, n1.w};
#pragma unroll
            for (int i = 0; i < 8; i++)
#pragma unroll
                for (int j = 0; j < 8; j++)
                    acc[i][j] += rm[i] * rn[j];
        }
        __syncthreads();
    }

    // epilogue: bias + store
    int gr = cRow + tr;
    int gc = cCol + tc;
    float4 bv0 = *(const float4*)&bias[gc];
    float4 bv1 = *(const float4*)&bias[gc + 4];
#pragma unroll
    for (int i = 0; i < 8; i++) {
        float4 o0, o1;
        o0.x = acc[i][0] + bv0.x; o0.y = acc[i][1] + bv0.y;
        o0.z = acc[i][2] + bv0.z; o0.w = acc[i][3] + bv0.w;
        o1.x = acc[i][4] + bv1.x; o1.y = acc[i][5] + bv1.y;
        o1.z = acc[i][6] + bv1.z; o1.w = acc[i][7] + bv1.w;
        float* cp = C + (size_t)(gr + i) * N + gc;
        *(float4*)cp       = o0;
        *(float4*)(cp + 4) = o1;
    }
}

// ---------------------------------------------------------------------------
// Flash attention (fp32): one CTA per (b, h, 128-row q-tile); one thread per
// query row; online softmax; K/V tiles of 64 rows streamed through SMEM.
// ---------------------------------------------------------------------------
#define QT   128
#define KT   64
#define QPAD 68   // row stride of Q tile in SMEM (float4-aligned, conflict-free)
#define PPAD 65   // row stride of probs tile (conflict-free scalar)

#define ATTN_SMEM_FLOATS (QT * QPAD + KT * 64 * 2 + QT * PPAD)
#define ATTN_SMEM_BYTES  (ATTN_SMEM_FLOATS * 4)

__global__ __launch_bounds__(128)
void attn_kernel(const float* __restrict__ Q, const float* __restrict__ Kp,
                 const float* __restrict__ Vp, float* __restrict__ Ctx)
{
    extern __shared__ float sm[];
    float* sq = sm;                      // [QT][QPAD]
    float* sk = sq + QT * QPAD;          // [KT][64]
    float* sv = sk + KT * 64;            // [KT][64]
    float* sp = sv + KT * 64;            // [QT][PPAD] probs staging

    int tid = threadIdx.x;
    int bh  = blockIdx.y;
    int b   = bh >> 4;      // H = 16
    int h   = bh & 15;
    int q0  = blockIdx.x * QT;

    const float* Qbase = Q  + ((size_t)(b * Ssz + q0)) * Dsz + h * DHsz;
    const float* Kbase = Kp + ((size_t)(b * Ssz))      * Dsz + h * DHsz;
    const float* Vbase = Vp + ((size_t)(b * Ssz))      * Dsz + h * DHsz;

    // load Q tile, pre-scaled by 1/sqrt(DH) = 0.125
    for (int i = tid; i < QT * 16; i += 128) {
        int row = i >> 4;
        int c   = (i & 15) * 4;
        float4 t = *(const float4*)(Qbase + (size_t)row * Dsz + c);
        float* dst = &sq[row * QPAD + c];
        dst[0] = t.x * 0.125f; dst[1] = t.y * 0.125f;
        dst[2] = t.z * 0.125f; dst[3] = t.w * 0.125f;
    }

    const int r = tid;      // this thread's query row within the tile
    float mcur = -1e30f, l = 0.f;
    float O[DHsz];
#pragma unroll
    for (int d = 0; d < DHsz; d++) O[d] = 0.f;

    for (int kt = 0; kt < Ssz; kt += KT) {
        __syncthreads();    // protect sk/sv reuse (also orders Q-tile fill, iter 0)
        for (int i = tid; i < KT * 16; i += 128) {
            int row = i >> 4;
            int c   = (i & 15) * 4;
            *(float4*)&sk[row * 64 + c] =
                *(const float4*)(Kbase + (size_t)(kt + row) * Dsz + c);
            *(float4*)&sv[row * 64 + c] =
                *(const float4*)(Vbase + (size_t)(kt + row) * Dsz + c);
        }
        __syncthreads();

        // scores: s[j] = q_row . k_j   (q pre-scaled)
        float s[KT];
#pragma unroll
        for (int j = 0; j < KT; j++) s[j] = 0.f;
#pragma unroll 1
        for (int d = 0; d < DHsz; d += 4) {
            float4 q4 = *(float4*)&sq[r * QPAD + d];
#pragma unroll
            for (int j = 0; j < KT; j++) {
                float4 k4 = *(float4*)&sk[j * 64 + d];   // broadcast across warp
                s[j] += q4.x * k4.x + q4.y * k4.y + q4.z * k4.z + q4.w * k4.w;
            }
        }

        // online softmax update
        float tmax = -1e30f;
#pragma unroll
        for (int j = 0; j < KT; j++) tmax = fmaxf(tmax, s[j]);
        float mnew = fmaxf(mcur, tmax);
        float corr = __expf(mcur - mnew);
        l *= corr;
#pragma unroll
        for (int d = 0; d < DHsz; d++) O[d] *= corr;
        float lad = 0.f;
#pragma unroll
        for (int j = 0; j < KT; j++) {
            float p = __expf(s[j] - mnew);
            lad += p;
            sp[r * PPAD + j] = p;    // stage probs (avoids dynamic reg indexing)
        }
        l += lad;
        mcur = mnew;

        // O += P @ V
#pragma unroll 1
        for (int j = 0; j < KT; j++) {
            float p = sp[r * PPAD + j];
#pragma unroll
            for (int d = 0; d < DHsz; d += 4) {
                float4 v4 = *(float4*)&sv[j * 64 + d];   // broadcast
                O[d]     += p * v4.x;
                O[d + 1] += p * v4.y;
                O[d + 2] += p * v4.z;
                O[d + 3] += p * v4.w;
            }
        }
    }

    float inv = 1.f / l;
    float* outp = Ctx + ((size_t)(b * Ssz + q0 + r)) * Dsz + h * DHsz;
#pragma unroll
    for (int d = 0; d < DHsz; d += 4) {
        float4 o;
        o.x = O[d] * inv;     o.y = O[d + 1] * inv;
        o.z = O[d + 2] * inv; o.w = O[d + 3] * inv;
        *(float4*)&outp[d] = o;
    }
}

// ---------------------------------------------------------------------------
extern "C" void kernel_launch(void* const* d_in, const int* in_sizes, int n_in,
                              void* d_out, int out_size)
{
    (void)in_sizes; (void)n_in; (void)out_size;
    const float* x  = (const float*)d_in[0];
    const float* Wq = (const float*)d_in[1];
    const float* bq = (const float*)d_in[2];
    const float* Wk = (const float*)d_in[3];
    const float* bk = (const float*)d_in[4];
    const float* Wv = (const float*)d_in[5];
    const float* bv = (const float*)d_in[6];
    const float* Wo = (const float*)d_in[7];
    const float* bo = (const float*)d_in[8];

    float *q, *k, *v, *ctx;
    cudaGetSymbolAddress((void**)&q,   g_q);
    cudaGetSymbolAddress((void**)&k,   g_k);
    cudaGetSymbolAddress((void**)&v,   g_v);
    cudaGetSymbolAddress((void**)&ctx, g_ctx);

    dim3 gg(Dsz / 128, Msz / 128);   // (8, 32)

    gemm_bias<1><<<gg, 256>>>(x, Wq, bq, q, Msz, Dsz, Dsz);
    gemm_bias<1><<<gg, 256>>>(x, Wk, bk, k, Msz, Dsz, Dsz);
    gemm_bias<1><<<gg, 256>>>(x, Wv, bv, v, Msz, Dsz, Dsz);

    cudaFuncSetAttribute(attn_kernel,
                         cudaFuncAttributeMaxDynamicSharedMemorySize,
                         ATTN_SMEM_BYTES);
    attn_kernel<<<dim3(Ssz / QT, Bsz * Hsz), 128, ATTN_SMEM_BYTES>>>(q, k, v, ctx);

    gemm_bias<0><<<gg, 256>>>(ctx, Wo, bo, (float*)d_out, Msz, Dsz, Dsz);
}

// round 4
// speedup vs baseline: 1.3806x; 1.3806x over previous
#include <cuda_runtime.h>
#include <math.h>
#include <stdint.h>

// Problem constants
#define Bsz  2
#define Ssz  2048
#define Dsz  1024
#define Hsz  16
#define DHsz 64
#define Msz  (Bsz * Ssz)   // 4096 rows

// Scratch: q/k/v/ctx all stored as [B*S, H*DH] row-major (head-blocked columns).
__device__ float g_q[Msz * Dsz];
__device__ float g_k[Msz * Dsz];
__device__ float g_v[Msz * Dsz];
__device__ float g_ctx[Msz * Dsz];

__device__ __forceinline__ uint32_t f2tf32(float x) {
    uint32_t r;
    asm("cvt.rna.tf32.f32 %0, %1;" : "=r"(r) : "f"(x));
    return r;
}

__device__ __forceinline__ void mma_tf32(float* c, const uint32_t* a, const uint32_t* b) {
    asm volatile(
        "mma.sync.aligned.m16n8k8.row.col.f32.tf32.tf32.f32 "
        "{%0,%1,%2,%3}, {%4,%5,%6,%7}, {%8,%9}, {%0,%1,%2,%3};"
        : "+f"(c[0]), "+f"(c[1]), "+f"(c[2]), "+f"(c[3])
        : "r"(a[0]), "r"(a[1]), "r"(a[2]), "r"(a[3]), "r"(b[0]), "r"(b[1]));
}

// ===========================================================================
// tf32 mma.sync GEMM + bias: C[M,N] = A[M,K] @ W + bias
//   HB=1: W head-blocked [H, K, DH]; HB=0: W row-major [K, N]
// 256 threads, CTA tile 128x128, BK=32, warp grid 4(M)x2(N), warp tile 32x64.
// SMEM: As[m][k] stride 36 (conflict-free A-frag reads),
//       Bs[k][n] stride 136 (conflict-free B-frag reads).
// ===========================================================================
#define ASTRIDE 36
#define BSTRIDE 136

template <int HB>
__global__ __launch_bounds__(256)
void gemm_mma(const float* __restrict__ A, const float* __restrict__ W,
              const float* __restrict__ bias, float* __restrict__ C,
              int M, int N, int K)
{
    __shared__ uint32_t As[128 * ASTRIDE];   // 18432 B
    __shared__ uint32_t Bs[32 * BSTRIDE];    // 17408 B

    const int tid  = threadIdx.x;
    const int lane = tid & 31;
    const int wid  = tid >> 5;
    const int warpM = wid >> 1;      // 0..3
    const int warpN = wid & 1;       // 0..1

    const int cRow = blockIdx.y * 128;
    const int cCol = blockIdx.x * 128;

    // gmem load mappings (4 float4 each for A and B per chunk)
    // A: idx -> row = idx>>3 (0..127), c = (idx&7)*4 (0..28)
    // B: idx -> kk  = idx>>5 (0..31),  n = (idx&31)*4 (0..124)
    float4 pa[4], pb[4];

    const int aRow[4] = { (tid + 0*256) >> 3, (tid + 1*256) >> 3,
                          (tid + 2*256) >> 3, (tid + 3*256) >> 3 };
    const int aC = (tid & 7) * 4;
    const int bKK[4] = { (tid + 0*256) >> 5, (tid + 1*256) >> 5,
                         (tid + 2*256) >> 5, (tid + 3*256) >> 5 };
    const int bN = (tid & 31) * 4;

    float acc[2][8][4];
#pragma unroll
    for (int i = 0; i < 2; i++)
#pragma unroll
        for (int j = 0; j < 8; j++)
#pragma unroll
            for (int l = 0; l < 4; l++) acc[i][j][l] = 0.f;

    const int m0 = warpM * 32;
    const int n0 = warpN * 64;
    const int grp = lane >> 2;   // 0..7
    const int thr = lane & 3;    // 0..3

    auto ldg = [&](int k0) {
#pragma unroll
        for (int t = 0; t < 4; t++)
            pa[t] = *(const float4*)(A + (size_t)(cRow + aRow[t]) * K + k0 + aC);
#pragma unroll
        for (int t = 0; t < 4; t++) {
            int n = cCol + bN;
            int kk = k0 + bKK[t];
            const float* wp;
            if (HB) wp = W + ((size_t)(n >> 6) * K + kk) * DHsz + (n & 63);
            else    wp = W + (size_t)kk * N + n;
            pb[t] = *(const float4*)wp;
        }
    };

    auto sts = [&]() {
#pragma unroll
        for (int t = 0; t < 4; t++) {
            uint4 u;
            u.x = f2tf32(pa[t].x); u.y = f2tf32(pa[t].y);
            u.z = f2tf32(pa[t].z); u.w = f2tf32(pa[t].w);
            *(uint4*)&As[aRow[t] * ASTRIDE + aC] = u;
        }
#pragma unroll
        for (int t = 0; t < 4; t++) {
            uint4 u;
            u.x = f2tf32(pb[t].x); u.y = f2tf32(pb[t].y);
            u.z = f2tf32(pb[t].z); u.w = f2tf32(pb[t].w);
            *(uint4*)&Bs[bKK[t] * BSTRIDE + bN] = u;
        }
    };

    auto compute = [&]() {
#pragma unroll
        for (int ks = 0; ks < 4; ks++) {
            const int kk = ks * 8;
            uint32_t af[2][4];
#pragma unroll
            for (int mt = 0; mt < 2; mt++) {
                int r = m0 + mt * 16 + grp;
                af[mt][0] = As[(r    ) * ASTRIDE + kk + thr    ];
                af[mt][1] = As[(r + 8) * ASTRIDE + kk + thr    ];
                af[mt][2] = As[(r    ) * ASTRIDE + kk + thr + 4];
                af[mt][3] = As[(r + 8) * ASTRIDE + kk + thr + 4];
            }
#pragma unroll
            for (int nt = 0; nt < 8; nt++) {
                uint32_t bf[2];
                int c = n0 + nt * 8 + grp;
                bf[0] = Bs[(kk + thr    ) * BSTRIDE + c];
                bf[1] = Bs[(kk + thr + 4) * BSTRIDE + c];
                mma_tf32(acc[0][nt], af[0], bf);
                mma_tf32(acc[1][nt], af[1], bf);
            }
        }
    };

    const int nchunks = K / 32;   // 32
    ldg(0);
    sts();
    __syncthreads();
    for (int i = 1; i < nchunks; i++) {
        ldg(i * 32);
        compute();
        __syncthreads();
        sts();
        __syncthreads();
    }
    compute();

    // Epilogue: bias + store. c0/c1 at (row, col/col+1), c2/c3 at row+8.
#pragma unroll
    for (int mt = 0; mt < 2; mt++) {
        int r0 = cRow + m0 + mt * 16 + grp;
#pragma unroll
        for (int nt = 0; nt < 8; nt++) {
            int col = cCol + n0 + nt * 8 + thr * 2;
            float b0 = bias[col], b1 = bias[col + 1];
            float2 v0 = { acc[mt][nt][0] + b0, acc[mt][nt][1] + b1 };
            float2 v1 = { acc[mt][nt][2] + b0, acc[mt][nt][3] + b1 };
            *(float2*)(C + (size_t)r0 * N + col)       = v0;
            *(float2*)(C + (size_t)(r0 + 8) * N + col) = v1;
        }
    }
}

// ---------------------------------------------------------------------------
// Flash attention (fp32) — unchanged from R1 baseline.
// ---------------------------------------------------------------------------
#define QT   128
#define KT   64
#define QPAD 68
#define PPAD 65

#define ATTN_SMEM_FLOATS (QT * QPAD + KT * 64 * 2 + QT * PPAD)
#define ATTN_SMEM_BYTES  (ATTN_SMEM_FLOATS * 4)

__global__ __launch_bounds__(128)
void attn_kernel(const float* __restrict__ Q, const float* __restrict__ Kp,
                 const float* __restrict__ Vp, float* __restrict__ Ctx)
{
    extern __shared__ float sm[];
    float* sq = sm;
    float* sk = sq + QT * QPAD;
    float* sv = sk + KT * 64;
    float* sp = sv + KT * 64;

    int tid = threadIdx.x;
    int bh  = blockIdx.y;
    int b   = bh >> 4;
    int h   = bh & 15;
    int q0  = blockIdx.x * QT;

    const float* Qbase = Q  + ((size_t)(b * Ssz + q0)) * Dsz + h * DHsz;
    const float* Kbase = Kp + ((size_t)(b * Ssz))      * Dsz + h * DHsz;
    const float* Vbase = Vp + ((size_t)(b * Ssz))      * Dsz + h * DHsz;

    for (int i = tid; i < QT * 16; i += 128) {
        int row = i >> 4;
        int c   = (i & 15) * 4;
        float4 t = *(const float4*)(Qbase + (size_t)row * Dsz + c);
        float* dst = &sq[row * QPAD + c];
        dst[0] = t.x * 0.125f; dst[1] = t.y * 0.125f;
        dst[2] = t.z * 0.125f; dst[3] = t.w * 0.125f;
    }

    const int r = tid;
    float mcur = -1e30f, l = 0.f;
    float O[DHsz];
#pragma unroll
    for (int d = 0; d < DHsz; d++) O[d] = 0.f;

    for (int kt = 0; kt < Ssz; kt += KT) {
        __syncthreads();
        for (int i = tid; i < KT * 16; i += 128) {
            int row = i >> 4;
            int c   = (i & 15) * 4;
            *(float4*)&sk[row * 64 + c] =
                *(const float4*)(Kbase + (size_t)(kt + row) * Dsz + c);
            *(float4*)&sv[row * 64 + c] =
                *(const float4*)(Vbase + (size_t)(kt + row) * Dsz + c);
        }
        __syncthreads();

        float s[KT];
#pragma unroll
        for (int j = 0; j < KT; j++) s[j] = 0.f;
#pragma unroll 1
        for (int d = 0; d < DHsz; d += 4) {
            float4 q4 = *(float4*)&sq[r * QPAD + d];
#pragma unroll
            for (int j = 0; j < KT; j++) {
                float4 k4 = *(float4*)&sk[j * 64 + d];
                s[j] += q4.x * k4.x + q4.y * k4.y + q4.z * k4.z + q4.w * k4.w;
            }
        }

        float tmax = -1e30f;
#pragma unroll
        for (int j = 0; j < KT; j++) tmax = fmaxf(tmax, s[j]);
        float mnew = fmaxf(mcur, tmax);
        float corr = __expf(mcur - mnew);
        l *= corr;
#pragma unroll
        for (int d = 0; d < DHsz; d++) O[d] *= corr;
        float lad = 0.f;
#pragma unroll
        for (int j = 0; j < KT; j++) {
            float p = __expf(s[j] - mnew);
            lad += p;
            sp[r * PPAD + j] = p;
        }
        l += lad;
        mcur = mnew;

#pragma unroll 1
        for (int j = 0; j < KT; j++) {
            float p = sp[r * PPAD + j];
#pragma unroll
            for (int d = 0; d < DHsz; d += 4) {
                float4 v4 = *(float4*)&sv[j * 64 + d];
                O[d]     += p * v4.x;
                O[d + 1] += p * v4.y;
                O[d + 2] += p * v4.z;
                O[d + 3] += p * v4.w;
            }
        }
    }

    float inv = 1.f / l;
    float* outp = Ctx + ((size_t)(b * Ssz + q0 + r)) * Dsz + h * DHsz;
#pragma unroll
    for (int d = 0; d < DHsz; d += 4) {
        float4 o;
        o.x = O[d] * inv;     o.y = O[d + 1] * inv;
        o.z = O[d + 2] * inv; o.w = O[d + 3] * inv;
        *(float4*)&outp[d] = o;
    }
}

// ---------------------------------------------------------------------------
extern "C" void kernel_launch(void* const* d_in, const int* in_sizes, int n_in,
                              void* d_out, int out_size)
{
    (void)in_sizes; (void)n_in; (void)out_size;
    const float* x  = (const float*)d_in[0];
    const float* Wq = (const float*)d_in[1];
    const float* bq = (const float*)d_in[2];
    const float* Wk = (const float*)d_in[3];
    const float* bk = (const float*)d_in[4];
    const float* Wv = (const float*)d_in[5];
    const float* bv = (const float*)d_in[6];
    const float* Wo = (const float*)d_in[7];
    const float* bo = (const float*)d_in[8];

    float *q, *k, *v, *ctx;
    cudaGetSymbolAddress((void**)&q,   g_q);
    cudaGetSymbolAddress((void**)&k,   g_k);
    cudaGetSymbolAddress((void**)&v,   g_v);
    cudaGetSymbolAddress((void**)&ctx, g_ctx);

    cudaFuncSetAttribute(attn_kernel,
                         cudaFuncAttributeMaxDynamicSharedMemorySize,
                         ATTN_SMEM_BYTES);

    dim3 gg(Dsz / 128, Msz / 128);   // (8, 32)

    gemm_mma<1><<<gg, 256>>>(x, Wq, bq, q, Msz, Dsz, Dsz);
    gemm_mma<1><<<gg, 256>>>(x, Wk, bk, k, Msz, Dsz, Dsz);
    gemm_mma<1><<<gg, 256>>>(x, Wv, bv, v, Msz, Dsz, Dsz);

    attn_kernel<<<dim3(Ssz / QT, Bsz * Hsz), 128, ATTN_SMEM_BYTES>>>(q, k, v, ctx);

    gemm_mma<0><<<gg, 256>>>(ctx, Wo, bo, (float*)d_out, Msz, Dsz, Dsz);
}

// round 5
// speedup vs baseline: 2.5303x; 1.8327x over previous
#include <cuda_runtime.h>
#include <math.h>
#include <stdint.h>

// Problem constants
#define Bsz  2
#define Ssz  2048
#define Dsz  1024
#define Hsz  16
#define DHsz 64
#define Msz  (Bsz * Ssz)   // 4096 rows

// Scratch: q/k/v/ctx all stored as [B*S, H*DH] row-major (head-blocked columns).
__device__ float g_q[Msz * Dsz];
__device__ float g_k[Msz * Dsz];
__device__ float g_v[Msz * Dsz];
__device__ float g_ctx[Msz * Dsz];

__device__ __forceinline__ uint32_t f2tf32(float x) {
    uint32_t r;
    asm("cvt.rna.tf32.f32 %0, %1;" : "=r"(r) : "f"(x));
    return r;
}

__device__ __forceinline__ void mma_tf32(float* c, const uint32_t* a, const uint32_t* b) {
    asm volatile(
        "mma.sync.aligned.m16n8k8.row.col.f32.tf32.tf32.f32 "
        "{%0,%1,%2,%3}, {%4,%5,%6,%7}, {%8,%9}, {%0,%1,%2,%3};"
        : "+f"(c[0]), "+f"(c[1]), "+f"(c[2]), "+f"(c[3])
        : "r"(a[0]), "r"(a[1]), "r"(a[2]), "r"(a[3]), "r"(b[0]), "r"(b[1]));
}

// ===========================================================================
// tf32 mma.sync GEMM + bias (unchanged from R3 — passing)
// ===========================================================================
#define ASTRIDE 36
#define BSTRIDE 136

template <int HB>
__global__ __launch_bounds__(256)
void gemm_mma(const float* __restrict__ A, const float* __restrict__ W,
              const float* __restrict__ bias, float* __restrict__ C,
              int M, int N, int K)
{
    __shared__ uint32_t As[128 * ASTRIDE];
    __shared__ uint32_t Bs[32 * BSTRIDE];

    const int tid  = threadIdx.x;
    const int lane = tid & 31;
    const int wid  = tid >> 5;
    const int warpM = wid >> 1;
    const int warpN = wid & 1;

    const int cRow = blockIdx.y * 128;
    const int cCol = blockIdx.x * 128;

    float4 pa[4], pb[4];

    const int aRow[4] = { (tid + 0*256) >> 3, (tid + 1*256) >> 3,
                          (tid + 2*256) >> 3, (tid + 3*256) >> 3 };
    const int aC = (tid & 7) * 4;
    const int bKK[4] = { (tid + 0*256) >> 5, (tid + 1*256) >> 5,
                         (tid + 2*256) >> 5, (tid + 3*256) >> 5 };
    const int bN = (tid & 31) * 4;

    float acc[2][8][4];
#pragma unroll
    for (int i = 0; i < 2; i++)
#pragma unroll
        for (int j = 0; j < 8; j++)
#pragma unroll
            for (int l = 0; l < 4; l++) acc[i][j][l] = 0.f;

    const int m0 = warpM * 32;
    const int n0 = warpN * 64;
    const int grp = lane >> 2;
    const int thr = lane & 3;

    auto ldg = [&](int k0) {
#pragma unroll
        for (int t = 0; t < 4; t++)
            pa[t] = *(const float4*)(A + (size_t)(cRow + aRow[t]) * K + k0 + aC);
#pragma unroll
        for (int t = 0; t < 4; t++) {
            int n = cCol + bN;
            int kk = k0 + bKK[t];
            const float* wp;
            if (HB) wp = W + ((size_t)(n >> 6) * K + kk) * DHsz + (n & 63);
            else    wp = W + (size_t)kk * N + n;
            pb[t] = *(const float4*)wp;
        }
    };

    auto sts = [&]() {
#pragma unroll
        for (int t = 0; t < 4; t++) {
            uint4 u;
            u.x = f2tf32(pa[t].x); u.y = f2tf32(pa[t].y);
            u.z = f2tf32(pa[t].z); u.w = f2tf32(pa[t].w);
            *(uint4*)&As[aRow[t] * ASTRIDE + aC] = u;
        }
#pragma unroll
        for (int t = 0; t < 4; t++) {
            uint4 u;
            u.x = f2tf32(pb[t].x); u.y = f2tf32(pb[t].y);
            u.z = f2tf32(pb[t].z); u.w = f2tf32(pb[t].w);
            *(uint4*)&Bs[bKK[t] * BSTRIDE + bN] = u;
        }
    };

    auto compute = [&]() {
#pragma unroll
        for (int ks = 0; ks < 4; ks++) {
            const int kk = ks * 8;
            uint32_t af[2][4];
#pragma unroll
            for (int mt = 0; mt < 2; mt++) {
                int r = m0 + mt * 16 + grp;
                af[mt][0] = As[(r    ) * ASTRIDE + kk + thr    ];
                af[mt][1] = As[(r + 8) * ASTRIDE + kk + thr    ];
                af[mt][2] = As[(r    ) * ASTRIDE + kk + thr + 4];
                af[mt][3] = As[(r + 8) * ASTRIDE + kk + thr + 4];
            }
#pragma unroll
            for (int nt = 0; nt < 8; nt++) {
                uint32_t bf[2];
                int c = n0 + nt * 8 + grp;
                bf[0] = Bs[(kk + thr    ) * BSTRIDE + c];
                bf[1] = Bs[(kk + thr + 4) * BSTRIDE + c];
                mma_tf32(acc[0][nt], af[0], bf);
                mma_tf32(acc[1][nt], af[1], bf);
            }
        }
    };

    const int nchunks = K / 32;
    ldg(0);
    sts();
    __syncthreads();
    for (int i = 1; i < nchunks; i++) {
        ldg(i * 32);
        compute();
        __syncthreads();
        sts();
        __syncthreads();
    }
    compute();

#pragma unroll
    for (int mt = 0; mt < 2; mt++) {
        int r0 = cRow + m0 + mt * 16 + grp;
#pragma unroll
        for (int nt = 0; nt < 8; nt++) {
            int col = cCol + n0 + nt * 8 + thr * 2;
            float b0 = bias[col], b1 = bias[col + 1];
            float2 v0 = { acc[mt][nt][0] + b0, acc[mt][nt][1] + b1 };
            float2 v1 = { acc[mt][nt][2] + b0, acc[mt][nt][3] + b1 };
            *(float2*)(C + (size_t)r0 * N + col)       = v0;
            *(float2*)(C + (size_t)(r0 + 8) * N + col) = v1;
        }
    }
}

// ===========================================================================
// Flash attention with tf32 mma.sync.
// 256 threads (8 warps), 128 q-rows/CTA (16 per warp), KT=64 key tiles.
// QK^T uses 2-term tf32 decomposition (qh*kh + ql*kh + qh*kl) for precision.
// PV single-pass tf32. fp32 online softmax in registers.
// SMEM strides chosen for conflict-free fragment LDS:
//   K tiles stride 68 (= 4 mod 32), V tile stride 72 (= 8 mod 32), P stride 68.
// ===========================================================================
#define AKS 68
#define AVS 72
#define APS 68

#define OFF_KH 0
#define OFF_KL (64 * AKS)
#define OFF_V  (OFF_KL + 64 * AKS)
#define OFF_P  (OFF_V + 64 * AVS)
#define ATTN_SMEM_U32   (OFF_P + 128 * APS)
#define ATTN_SMEM_BYTES (ATTN_SMEM_U32 * 4)   // 88064

__global__ __launch_bounds__(256)
void attn_mma(const float* __restrict__ Q, const float* __restrict__ Kp,
              const float* __restrict__ Vp, float* __restrict__ Ctx)
{
    extern __shared__ uint32_t smu[];
    uint32_t* skh = smu + OFF_KH;
    uint32_t* skl = smu + OFF_KL;
    uint32_t* svv = smu + OFF_V;
    uint32_t* spq = smu + OFF_P;    // Q staging (fp32), then per-warp P tiles

    const int tid  = threadIdx.x;
    const int lane = tid & 31;
    const int wid  = tid >> 5;
    const int grp  = lane >> 2;
    const int thr  = lane & 3;

    const int bh = blockIdx.y;
    const int b  = bh >> 4;
    const int h  = bh & 15;
    const int q0 = blockIdx.x * 128;

    const float* Qbase = Q  + ((size_t)(b * Ssz + q0)) * Dsz + h * DHsz;
    const float* Kbase = Kp + ((size_t)(b * Ssz))      * Dsz + h * DHsz;
    const float* Vbase = Vp + ((size_t)(b * Ssz))      * Dsz + h * DHsz;

    // Stage Q (pre-scaled by 1/8) as fp32 into spq [128][APS]
    float* qstage = (float*)spq;
    for (int i = tid; i < 128 * 16; i += 256) {
        int row = i >> 4;
        int c   = (i & 15) * 4;
        float4 t = *(const float4*)(Qbase + (size_t)row * Dsz + c);
        float* dst = &qstage[row * APS + c];
        dst[0] = t.x * 0.125f; dst[1] = t.y * 0.125f;
        dst[2] = t.z * 0.125f; dst[3] = t.w * 0.125f;
    }
    __syncthreads();

    // Build Q fragments (hi + lo) in registers. Warp w owns rows [16w, 16w+16).
    uint32_t qh[8][4], ql[8][4];
    const int qr = wid * 16 + grp;
#pragma unroll
    for (int ks = 0; ks < 8; ks++) {
        float f0 = qstage[(qr    ) * APS + ks * 8 + thr    ];
        float f1 = qstage[(qr + 8) * APS + ks * 8 + thr    ];
        float f2 = qstage[(qr    ) * APS + ks * 8 + thr + 4];
        float f3 = qstage[(qr + 8) * APS + ks * 8 + thr + 4];
        qh[ks][0] = f2tf32(f0); ql[ks][0] = f2tf32(f0 - __uint_as_float(qh[ks][0]));
        qh[ks][1] = f2tf32(f1); ql[ks][1] = f2tf32(f1 - __uint_as_float(qh[ks][1]));
        qh[ks][2] = f2tf32(f2); ql[ks][2] = f2tf32(f2 - __uint_as_float(qh[ks][2]));
        qh[ks][3] = f2tf32(f3); ql[ks][3] = f2tf32(f3 - __uint_as_float(qh[ks][3]));
    }

    float O[8][4];
#pragma unroll
    for (int nt = 0; nt < 8; nt++)
#pragma unroll
        for (int l = 0; l < 4; l++) O[nt][l] = 0.f;
    float m0v = -1e30f, m1v = -1e30f, l0 = 0.f, l1 = 0.f;

    uint32_t* spw = spq + wid * 16 * APS;   // this warp's P tile (overwrites its own Q stage rows)

    for (int kt = 0; kt < Ssz; kt += 64) {
        __syncthreads();   // prior PV reads of svv done; also orders Q staging reads (iter 0)
        // Load K (hi/lo) and V (tf32) tiles: 64 rows x 64 dims
        for (int i = tid; i < 64 * 16; i += 256) {
            int row = i >> 4;
            int c   = (i & 15) * 4;
            float4 kx = *(const float4*)(Kbase + (size_t)(kt + row) * Dsz + c);
            float4 vx = *(const float4*)(Vbase + (size_t)(kt + row) * Dsz + c);
            uint4 uh, ul, uv;
            uh.x = f2tf32(kx.x); ul.x = f2tf32(kx.x - __uint_as_float(uh.x));
            uh.y = f2tf32(kx.y); ul.y = f2tf32(kx.y - __uint_as_float(uh.y));
            uh.z = f2tf32(kx.z); ul.z = f2tf32(kx.z - __uint_as_float(uh.z));
            uh.w = f2tf32(kx.w); ul.w = f2tf32(kx.w - __uint_as_float(uh.w));
            uv.x = f2tf32(vx.x); uv.y = f2tf32(vx.y);
            uv.z = f2tf32(vx.z); uv.w = f2tf32(vx.w);
            *(uint4*)&skh[row * AKS + c] = uh;
            *(uint4*)&skl[row * AKS + c] = ul;
            *(uint4*)&svv[row * AVS + c] = uv;
        }
        __syncthreads();

        // S = Q K^T (warp tile 16 x 64), 3-term tf32
        float S[8][4];
#pragma unroll
        for (int nt = 0; nt < 8; nt++)
#pragma unroll
            for (int l = 0; l < 4; l++) S[nt][l] = 0.f;

#pragma unroll
        for (int ks = 0; ks < 8; ks++) {
#pragma unroll
            for (int nt = 0; nt < 8; nt++) {
                int krow = nt * 8 + grp;
                uint32_t bhf[2], blf[2];
                bhf[0] = skh[krow * AKS + ks * 8 + thr];
                bhf[1] = skh[krow * AKS + ks * 8 + thr + 4];
                blf[0] = skl[krow * AKS + ks * 8 + thr];
                blf[1] = skl[krow * AKS + ks * 8 + thr + 4];
                mma_tf32(S[nt], qh[ks], bhf);
                mma_tf32(S[nt], ql[ks], bhf);
                mma_tf32(S[nt], qh[ks], blf);
            }
        }

        // Online softmax (rows qr and qr+8)
        float mx0 = -1e30f, mx1 = -1e30f;
#pragma unroll
        for (int nt = 0; nt < 8; nt++) {
            mx0 = fmaxf(mx0, fmaxf(S[nt][0], S[nt][1]));
            mx1 = fmaxf(mx1, fmaxf(S[nt][2], S[nt][3]));
        }
        mx0 = fmaxf(mx0, __shfl_xor_sync(0xffffffffu, mx0, 1));
        mx0 = fmaxf(mx0, __shfl_xor_sync(0xffffffffu, mx0, 2));
        mx1 = fmaxf(mx1, __shfl_xor_sync(0xffffffffu, mx1, 1));
        mx1 = fmaxf(mx1, __shfl_xor_sync(0xffffffffu, mx1, 2));

        float mn0 = fmaxf(m0v, mx0), mn1 = fmaxf(m1v, mx1);
        float c0 = __expf(m0v - mn0), c1 = __expf(m1v - mn1);

        float s0 = 0.f, s1 = 0.f;
#pragma unroll
        for (int nt = 0; nt < 8; nt++) {
            uint32_t t00 = f2tf32(__expf(S[nt][0] - mn0));
            uint32_t t01 = f2tf32(__expf(S[nt][1] - mn0));
            uint32_t t10 = f2tf32(__expf(S[nt][2] - mn1));
            uint32_t t11 = f2tf32(__expf(S[nt][3] - mn1));
            s0 += __uint_as_float(t00) + __uint_as_float(t01);
            s1 += __uint_as_float(t10) + __uint_as_float(t11);
            uint2 p0 = {t00, t01}, p1 = {t10, t11};
            *(uint2*)&spw[(grp    ) * APS + nt * 8 + 2 * thr] = p0;
            *(uint2*)&spw[(grp + 8) * APS + nt * 8 + 2 * thr] = p1;
        }
        s0 += __shfl_xor_sync(0xffffffffu, s0, 1);
        s0 += __shfl_xor_sync(0xffffffffu, s0, 2);
        s1 += __shfl_xor_sync(0xffffffffu, s1, 1);
        s1 += __shfl_xor_sync(0xffffffffu, s1, 2);

        l0 = l0 * c0 + s0;
        l1 = l1 * c1 + s1;
        m0v = mn0; m1v = mn1;

#pragma unroll
        for (int nt = 0; nt < 8; nt++) {
            O[nt][0] *= c0; O[nt][1] *= c0;
            O[nt][2] *= c1; O[nt][3] *= c1;
        }
        __syncwarp();

        // O += P V  (K-dim = 64 keys)
#pragma unroll
        for (int ks = 0; ks < 8; ks++) {
            uint32_t a[4];
            a[0] = spw[(grp    ) * APS + ks * 8 + thr    ];
            a[1] = spw[(grp + 8) * APS + ks * 8 + thr    ];
            a[2] = spw[(grp    ) * APS + ks * 8 + thr + 4];
            a[3] = spw[(grp + 8) * APS + ks * 8 + thr + 4];
#pragma unroll
            for (int nt = 0; nt < 8; nt++) {
                uint32_t bb[2];
                bb[0] = svv[(ks * 8 + thr    ) * AVS + nt * 8 + grp];
                bb[1] = svv[(ks * 8 + thr + 4) * AVS + nt * 8 + grp];
                mma_tf32(O[nt], a, bb);
            }
        }
        __syncwarp();   // P reads done before next iteration's P writes
    }

    // Epilogue
    float i0 = 1.f / l0, i1 = 1.f / l1;
    int rowg = b * Ssz + q0 + wid * 16 + grp;
#pragma unroll
    for (int nt = 0; nt < 8; nt++) {
        int col = h * DHsz + nt * 8 + 2 * thr;
        float2 v0 = { O[nt][0] * i0, O[nt][1] * i0 };
        float2 v1 = { O[nt][2] * i1, O[nt][3] * i1 };
        *(float2*)(Ctx + (size_t)rowg * Dsz + col)       = v0;
        *(float2*)(Ctx + (size_t)(rowg + 8) * Dsz + col) = v1;
    }
}

// ---------------------------------------------------------------------------
extern "C" void kernel_launch(void* const* d_in, const int* in_sizes, int n_in,
                              void* d_out, int out_size)
{
    (void)in_sizes; (void)n_in; (void)out_size;
    const float* x  = (const float*)d_in[0];
    const float* Wq = (const float*)d_in[1];
    const float* bq = (const float*)d_in[2];
    const float* Wk = (const float*)d_in[3];
    const float* bk = (const float*)d_in[4];
    const float* Wv = (const float*)d_in[5];
    const float* bv = (const float*)d_in[6];
    const float* Wo = (const float*)d_in[7];
    const float* bo = (const float*)d_in[8];

    float *q, *k, *v, *ctx;
    cudaGetSymbolAddress((void**)&q,   g_q);
    cudaGetSymbolAddress((void**)&k,   g_k);
    cudaGetSymbolAddress((void**)&v,   g_v);
    cudaGetSymbolAddress((void**)&ctx, g_ctx);

    cudaFuncSetAttribute(attn_mma,
                         cudaFuncAttributeMaxDynamicSharedMemorySize,
                         ATTN_SMEM_BYTES);

    dim3 gg(Dsz / 128, Msz / 128);   // (8, 32)

    gemm_mma<1><<<gg, 256>>>(x, Wq, bq, q, Msz, Dsz, Dsz);
    gemm_mma<1><<<gg, 256>>>(x, Wk, bk, k, Msz, Dsz, Dsz);
    gemm_mma<1><<<gg, 256>>>(x, Wv, bv, v, Msz, Dsz, Dsz);

    attn_mma<<<dim3(Ssz / 128, Bsz * Hsz), 256, ATTN_SMEM_BYTES>>>(q, k, v, ctx);

    gemm_mma<0><<<gg, 256>>>(ctx, Wo, bo, (float*)d_out, Msz, Dsz, Dsz);
}

// round 6
// speedup vs baseline: 3.4003x; 1.3438x over previous
#include <cuda_runtime.h>
#include <math.h>
#include <stdint.h>

// Problem constants
#define Bsz  2
#define Ssz  2048
#define Dsz  1024
#define Hsz  16
#define DHsz 64
#define Msz  (Bsz * Ssz)   // 4096 rows

// Scratch: q/k/v/ctx all stored as [B*S, H*DH] row-major (head-blocked columns).
__device__ float g_q[Msz * Dsz];
__device__ float g_k[Msz * Dsz];
__device__ float g_v[Msz * Dsz];
__device__ float g_ctx[Msz * Dsz];

__device__ __forceinline__ uint32_t f2tf32(float x) {
    uint32_t r;
    asm("cvt.rna.tf32.f32 %0, %1;" : "=r"(r) : "f"(x));
    return r;
}

__device__ __forceinline__ void mma_tf32(float* c, const uint32_t* a, const uint32_t* b) {
    asm volatile(
        "mma.sync.aligned.m16n8k8.row.col.f32.tf32.tf32.f32 "
        "{%0,%1,%2,%3}, {%4,%5,%6,%7}, {%8,%9}, {%0,%1,%2,%3};"
        : "+f"(c[0]), "+f"(c[1]), "+f"(c[2]), "+f"(c[3])
        : "r"(a[0]), "r"(a[1]), "r"(a[2]), "r"(a[3]), "r"(b[0]), "r"(b[1]));
}

// ===========================================================================
// tf32 mma.sync GEMM + bias (unchanged — passing)
// ===========================================================================
#define ASTRIDE 36
#define BSTRIDE 136

template <int HB>
__global__ __launch_bounds__(256)
void gemm_mma(const float* __restrict__ A, const float* __restrict__ W,
              const float* __restrict__ bias, float* __restrict__ C,
              int M, int N, int K)
{
    __shared__ uint32_t As[128 * ASTRIDE];
    __shared__ uint32_t Bs[32 * BSTRIDE];

    const int tid  = threadIdx.x;
    const int lane = tid & 31;
    const int wid  = tid >> 5;
    const int warpM = wid >> 1;
    const int warpN = wid & 1;

    const int cRow = blockIdx.y * 128;
    const int cCol = blockIdx.x * 128;

    float4 pa[4], pb[4];

    const int aRow[4] = { (tid + 0*256) >> 3, (tid + 1*256) >> 3,
                          (tid + 2*256) >> 3, (tid + 3*256) >> 3 };
    const int aC = (tid & 7) * 4;
    const int bKK[4] = { (tid + 0*256) >> 5, (tid + 1*256) >> 5,
                         (tid + 2*256) >> 5, (tid + 3*256) >> 5 };
    const int bN = (tid & 31) * 4;

    float acc[2][8][4];
#pragma unroll
    for (int i = 0; i < 2; i++)
#pragma unroll
        for (int j = 0; j < 8; j++)
#pragma unroll
            for (int l = 0; l < 4; l++) acc[i][j][l] = 0.f;

    const int m0 = warpM * 32;
    const int n0 = warpN * 64;
    const int grp = lane >> 2;
    const int thr = lane & 3;

    auto ldg = [&](int k0) {
#pragma unroll
        for (int t = 0; t < 4; t++)
            pa[t] = *(const float4*)(A + (size_t)(cRow + aRow[t]) * K + k0 + aC);
#pragma unroll
        for (int t = 0; t < 4; t++) {
            int n = cCol + bN;
            int kk = k0 + bKK[t];
            const float* wp;
            if (HB) wp = W + ((size_t)(n >> 6) * K + kk) * DHsz + (n & 63);
            else    wp = W + (size_t)kk * N + n;
            pb[t] = *(const float4*)wp;
        }
    };

    auto sts = [&]() {
#pragma unroll
        for (int t = 0; t < 4; t++) {
            uint4 u;
            u.x = f2tf32(pa[t].x); u.y = f2tf32(pa[t].y);
            u.z = f2tf32(pa[t].z); u.w = f2tf32(pa[t].w);
            *(uint4*)&As[aRow[t] * ASTRIDE + aC] = u;
        }
#pragma unroll
        for (int t = 0; t < 4; t++) {
            uint4 u;
            u.x = f2tf32(pb[t].x); u.y = f2tf32(pb[t].y);
            u.z = f2tf32(pb[t].z); u.w = f2tf32(pb[t].w);
            *(uint4*)&Bs[bKK[t] * BSTRIDE + bN] = u;
        }
    };

    auto compute = [&]() {
#pragma unroll
        for (int ks = 0; ks < 4; ks++) {
            const int kk = ks * 8;
            uint32_t af[2][4];
#pragma unroll
            for (int mt = 0; mt < 2; mt++) {
                int r = m0 + mt * 16 + grp;
                af[mt][0] = As[(r    ) * ASTRIDE + kk + thr    ];
                af[mt][1] = As[(r + 8) * ASTRIDE + kk + thr    ];
                af[mt][2] = As[(r    ) * ASTRIDE + kk + thr + 4];
                af[mt][3] = As[(r + 8) * ASTRIDE + kk + thr + 4];
            }
#pragma unroll
            for (int nt = 0; nt < 8; nt++) {
                uint32_t bf[2];
                int c = n0 + nt * 8 + grp;
                bf[0] = Bs[(kk + thr    ) * BSTRIDE + c];
                bf[1] = Bs[(kk + thr + 4) * BSTRIDE + c];
                mma_tf32(acc[0][nt], af[0], bf);
                mma_tf32(acc[1][nt], af[1], bf);
            }
        }
    };

    const int nchunks = K / 32;
    ldg(0);
    sts();
    __syncthreads();
    for (int i = 1; i < nchunks; i++) {
        ldg(i * 32);
        compute();
        __syncthreads();
        sts();
        __syncthreads();
    }
    compute();

#pragma unroll
    for (int mt = 0; mt < 2; mt++) {
        int r0 = cRow + m0 + mt * 16 + grp;
#pragma unroll
        for (int nt = 0; nt < 8; nt++) {
            int col = cCol + n0 + nt * 8 + thr * 2;
            float b0 = bias[col], b1 = bias[col + 1];
            float2 v0 = { acc[mt][nt][0] + b0, acc[mt][nt][1] + b1 };
            float2 v1 = { acc[mt][nt][2] + b0, acc[mt][nt][3] + b1 };
            *(float2*)(C + (size_t)r0 * N + col)       = v0;
            *(float2*)(C + (size_t)(r0 + 8) * N + col) = v1;
        }
    }
}

// ===========================================================================
// Flash attention, tf32 mma.sync, fragment-ordered K/V smem.
// 256 threads (8 warps), 128 q-rows/CTA (16/warp), 64-key tiles.
// QK^T = qh*kh + ql*kh (2-term tf32; K hi only). PV single tf32.
// K frag layout: word((nt,grp),thr,w) = (nt*8+grp)*80 + thr*16
//                + 4*((w>>2)^q) + (w&3),  w = ks*2+half, q=(thr>>1)|((grp&1)<<1)
// V frag layout: same with (ks,grp) blocks and w = nt*2+half.
// grp-stride 80 (=16 mod 32) + quad XOR => conflict-free STS.32 writes and
// LDS.128 fragment reads. Global K/V loads double-buffered through registers.
// ===========================================================================
#define APS 68
#define OFF_KF 0
#define OFF_VF 5120
#define OFF_QP 10240
#define ATTN_SMEM_U32   (OFF_QP + 128 * APS)     // 18944 words
#define ATTN_SMEM_BYTES (ATTN_SMEM_U32 * 4)      // 75776 B

__global__ __launch_bounds__(256)
void attn_mma(const float* __restrict__ Q, const float* __restrict__ Kp,
              const float* __restrict__ Vp, float* __restrict__ Ctx)
{
    extern __shared__ uint32_t smu[];
    uint32_t* skf = smu + OFF_KF;
    uint32_t* svf = smu + OFF_VF;
    uint32_t* spq = smu + OFF_QP;   // Q staging (fp32), then per-warp P tiles

    const int tid  = threadIdx.x;
    const int lane = tid & 31;
    const int wid  = tid >> 5;
    const int grp  = lane >> 2;
    const int thr  = lane & 3;
    const int q_   = (thr >> 1) | ((grp & 1) << 1);

    const int bh = blockIdx.y;
    const int b  = bh >> 4;
    const int h  = bh & 15;
    const int q0 = blockIdx.x * 128;

    const float* Qbase = Q  + ((size_t)(b * Ssz + q0)) * Dsz + h * DHsz;
    const float* Kbase = Kp + ((size_t)(b * Ssz))      * Dsz + h * DHsz;
    const float* Vbase = Vp + ((size_t)(b * Ssz))      * Dsz + h * DHsz;

    // Stage Q (pre-scaled by 1/8) as fp32
    float* qstage = (float*)spq;
    for (int i = tid; i < 128 * 16; i += 256) {
        int row = i >> 4;
        int c   = (i & 15) * 4;
        float4 t = *(const float4*)(Qbase + (size_t)row * Dsz + c);
        float* dst = &qstage[row * APS + c];
        dst[0] = t.x * 0.125f; dst[1] = t.y * 0.125f;
        dst[2] = t.z * 0.125f; dst[3] = t.w * 0.125f;
    }
    __syncthreads();

    // Q fragments (hi + lo) in registers. Warp w owns rows [16w, 16w+16).
    uint32_t qh[8][4], ql[8][4];
    const int qr = wid * 16 + grp;
#pragma unroll
    for (int ks = 0; ks < 8; ks++) {
        float f0 = qstage[(qr    ) * APS + ks * 8 + thr    ];
        float f1 = qstage[(qr + 8) * APS + ks * 8 + thr    ];
        float f2 = qstage[(qr    ) * APS + ks * 8 + thr + 4];
        float f3 = qstage[(qr + 8) * APS + ks * 8 + thr + 4];
        qh[ks][0] = f2tf32(f0); ql[ks][0] = f2tf32(f0 - __uint_as_float(qh[ks][0]));
        qh[ks][1] = f2tf32(f1); ql[ks][1] = f2tf32(f1 - __uint_as_float(qh[ks][1]));
        qh[ks][2] = f2tf32(f2); ql[ks][2] = f2tf32(f2 - __uint_as_float(qh[ks][2]));
        qh[ks][3] = f2tf32(f3); ql[ks][3] = f2tf32(f3 - __uint_as_float(qh[ks][3]));
    }

    float O[8][4];
#pragma unroll
    for (int nt = 0; nt < 8; nt++)
#pragma unroll
        for (int l = 0; l < 4; l++) O[nt][l] = 0.f;
    float m0v = -1e30f, m1v = -1e30f, l0 = 0.f, l1 = 0.f;

    uint32_t* spw = spq + wid * 16 * APS;    // per-warp P tile

    // Per-thread tile-load geometry: 4 iters of (row, c)
    const int ldRow = tid >> 4;        // +16 per iter
    const int ldC   = (tid & 15) * 4;

    float4 pk[4], pv[4];
#pragma unroll
    for (int t = 0; t < 4; t++) {
        pk[t] = *(const float4*)(Kbase + (size_t)(ldRow + 16 * t) * Dsz + ldC);
        pv[t] = *(const float4*)(Vbase + (size_t)(ldRow + 16 * t) * Dsz + ldC);
    }

    for (int kt = 0; kt < Ssz; kt += 64) {
        __syncthreads();   // prior ktile's frag reads done

        // Store K/V fragments (scalar STS, conflict-free by construction)
#pragma unroll
        for (int t = 0; t < 4; t++) {
            int row = ldRow + 16 * t;
            // K: nt block = row>>3, grp' = row&7; w = ldC>>2
            {
                int ntb = row >> 3, gk = row & 7;
                int w = ldC >> 2;
                uint32_t blk = (uint32_t)((ntb * 8 + gk) * 80);
                uint32_t wlo = (uint32_t)(w & 3);
                uint32_t whi = (uint32_t)(w >> 2);
                uint32_t vals[4] = { f2tf32(pk[t].x), f2tf32(pk[t].y),
                                     f2tf32(pk[t].z), f2tf32(pk[t].w) };
#pragma unroll
                for (int j = 0; j < 4; j++) {
                    uint32_t qj = (uint32_t)((j >> 1) | ((gk & 1) << 1));
                    skf[blk + j * 16 + 4 * (whi ^ qj) + wlo] = vals[j];
                }
            }
            // V: ks block = row>>3, thr' = row&3, half = (row>>2)&1
            {
                int ksb = row >> 3, tv = row & 3, hv = (row >> 2) & 1;
                uint32_t vals[4] = { f2tf32(pv[t].x), f2tf32(pv[t].y),
                                     f2tf32(pv[t].z), f2tf32(pv[t].w) };
#pragma unroll
                for (int j = 0; j < 4; j++) {
                    int col = ldC + j;
                    int gv = col & 7, ntv = col >> 3;
                    int wv = ntv * 2 + hv;
                    uint32_t qv = (uint32_t)((tv >> 1) | ((gv & 1) << 1));
                    svf[(uint32_t)((ksb * 8 + gv) * 80 + tv * 16)
                        + 4 * ((uint32_t)(wv >> 2) ^ qv) + (uint32_t)(wv & 3)] = vals[j];
                }
            }
        }
        __syncthreads();

        // Prefetch next tile
        if (kt + 64 < Ssz) {
#pragma unroll
            for (int t = 0; t < 4; t++) {
                pk[t] = *(const float4*)(Kbase + (size_t)(kt + 64 + ldRow + 16 * t) * Dsz + ldC);
                pv[t] = *(const float4*)(Vbase + (size_t)(kt + 64 + ldRow + 16 * t) * Dsz + ldC);
            }
        }

        // ---- S = Q K^T (16 x 64 per warp), 2-term tf32 ----
        float S[8][4];
#pragma unroll
        for (int nt = 0; nt < 8; nt++)
#pragma unroll
            for (int l = 0; l < 4; l++) S[nt][l] = 0.f;

#pragma unroll
        for (int nt = 0; nt < 8; nt++) {
            uint32_t base = (uint32_t)((nt * 8 + grp) * 80 + thr * 16);
            uint4 G[4];
#pragma unroll
            for (int p = 0; p < 4; p++)
                G[p] = *(const uint4*)&skf[base + (uint32_t)((4 * p) ^ (4 * q_))];
#pragma unroll
            for (int p = 0; p < 4; p++) {
                uint32_t b0[2] = { G[p].x, G[p].y };
                uint32_t b1[2] = { G[p].z, G[p].w };
                mma_tf32(S[nt], qh[2 * p],     b0);
                mma_tf32(S[nt], ql[2 * p],     b0);
                mma_tf32(S[nt], qh[2 * p + 1], b1);
                mma_tf32(S[nt], ql[2 * p + 1], b1);
            }
        }

        // ---- online softmax (rows qr, qr+8) ----
        float mx0 = -1e30f, mx1 = -1e30f;
#pragma unroll
        for (int nt = 0; nt < 8; nt++) {
            mx0 = fmaxf(mx0, fmaxf(S[nt][0], S[nt][1]));
            mx1 = fmaxf(mx1, fmaxf(S[nt][2], S[nt][3]));
        }
        mx0 = fmaxf(mx0, __shfl_xor_sync(0xffffffffu, mx0, 1));
        mx0 = fmaxf(mx0, __shfl_xor_sync(0xffffffffu, mx0, 2));
        mx1 = fmaxf(mx1, __shfl_xor_sync(0xffffffffu, mx1, 1));
        mx1 = fmaxf(mx1, __shfl_xor_sync(0xffffffffu, mx1, 2));

        float mn0 = fmaxf(m0v, mx0), mn1 = fmaxf(m1v, mx1);
        float c0 = __expf(m0v - mn0), c1 = __expf(m1v - mn1);

        float s0 = 0.f, s1 = 0.f;
#pragma unroll
        for (int nt = 0; nt < 8; nt++) {
            uint32_t t00 = f2tf32(__expf(S[nt][0] - mn0));
            uint32_t t01 = f2tf32(__expf(S[nt][1] - mn0));
            uint32_t t10 = f2tf32(__expf(S[nt][2] - mn1));
            uint32_t t11 = f2tf32(__expf(S[nt][3] - mn1));
            s0 += __uint_as_float(t00) + __uint_as_float(t01);
            s1 += __uint_as_float(t10) + __uint_as_float(t11);
            uint2 p0 = { t00, t01 }, p1 = { t10, t11 };
            *(uint2*)&spw[(grp    ) * APS + nt * 8 + 2 * thr] = p0;
            *(uint2*)&spw[(grp + 8) * APS + nt * 8 + 2 * thr] = p1;
        }
        s0 += __shfl_xor_sync(0xffffffffu, s0, 1);
        s0 += __shfl_xor_sync(0xffffffffu, s0, 2);
        s1 += __shfl_xor_sync(0xffffffffu, s1, 1);
        s1 += __shfl_xor_sync(0xffffffffu, s1, 2);

        l0 = l0 * c0 + s0;
        l1 = l1 * c1 + s1;
        m0v = mn0; m1v = mn1;

#pragma unroll
        for (int nt = 0; nt < 8; nt++) {
            O[nt][0] *= c0; O[nt][1] *= c0;
            O[nt][2] *= c1; O[nt][3] *= c1;
        }
        __syncwarp();

        // ---- O += P V ----
#pragma unroll
        for (int ks = 0; ks < 8; ks++) {
            uint32_t a[4];
            a[0] = spw[(grp    ) * APS + ks * 8 + thr    ];
            a[1] = spw[(grp + 8) * APS + ks * 8 + thr    ];
            a[2] = spw[(grp    ) * APS + ks * 8 + thr + 4];
            a[3] = spw[(grp + 8) * APS + ks * 8 + thr + 4];
            uint32_t base = (uint32_t)((ks * 8 + grp) * 80 + thr * 16);
            uint4 G[4];
#pragma unroll
            for (int p = 0; p < 4; p++)
                G[p] = *(const uint4*)&svf[base + (uint32_t)((4 * p) ^ (4 * q_))];
#pragma unroll
            for (int p = 0; p < 4; p++) {
                uint32_t b0[2] = { G[p].x, G[p].y };
                uint32_t b1[2] = { G[p].z, G[p].w };
                mma_tf32(O[2 * p],     a, b0);
                mma_tf32(O[2 * p + 1], a, b1);
            }
        }
        __syncwarp();   // P reads done before next iteration's P writes
    }

    // Epilogue
    float i0 = 1.f / l0, i1 = 1.f / l1;
    int rowg = b * Ssz + q0 + wid * 16 + grp;
#pragma unroll
    for (int nt = 0; nt < 8; nt++) {
        int col = h * DHsz + nt * 8 + 2 * thr;
        float2 v0 = { O[nt][0] * i0, O[nt][1] * i0 };
        float2 v1 = { O[nt][2] * i1, O[nt][3] * i1 };
        *(float2*)(Ctx + (size_t)rowg * Dsz + col)       = v0;
        *(float2*)(Ctx + (size_t)(rowg + 8) * Dsz + col) = v1;
    }
}

// ---------------------------------------------------------------------------
extern "C" void kernel_launch(void* const* d_in, const int* in_sizes, int n_in,
                              void* d_out, int out_size)
{
    (void)in_sizes; (void)n_in; (void)out_size;
    const float* x  = (const float*)d_in[0];
    const float* Wq = (const float*)d_in[1];
    const float* bq = (const float*)d_in[2];
    const float* Wk = (const float*)d_in[3];
    const float* bk = (const float*)d_in[4];
    const float* Wv = (const float*)d_in[5];
    const float* bv = (const float*)d_in[6];
    const float* Wo = (const float*)d_in[7];
    const float* bo = (const float*)d_in[8];

    float *q, *k, *v, *ctx;
    cudaGetSymbolAddress((void**)&q,   g_q);
    cudaGetSymbolAddress((void**)&k,   g_k);
    cudaGetSymbolAddress((void**)&v,   g_v);
    cudaGetSymbolAddress((void**)&ctx, g_ctx);

    cudaFuncSetAttribute(attn_mma,
                         cudaFuncAttributeMaxDynamicSharedMemorySize,
                         ATTN_SMEM_BYTES);

    dim3 gg(Dsz / 128, Msz / 128);   // (8, 32)

    gemm_mma<1><<<gg, 256>>>(x, Wq, bq, q, Msz, Dsz, Dsz);
    gemm_mma<1><<<gg, 256>>>(x, Wk, bk, k, Msz, Dsz, Dsz);
    gemm_mma<1><<<gg, 256>>>(x, Wv, bv, v, Msz, Dsz, Dsz);

    attn_mma<<<dim3(Ssz / 128, Bsz * Hsz), 256, ATTN_SMEM_BYTES>>>(q, k, v, ctx);

    gemm_mma<0><<<gg, 256>>>(ctx, Wo, bo, (float*)d_out, Msz, Dsz, Dsz);
}